// round 5
// baseline (speedup 1.0000x reference)
#include <cuda_runtime.h>
#include <math.h>

#define BATCH 4096
#define NPAIR (BATCH / 2)

typedef unsigned long long u64;

// ---- packed fp32x2 helpers (sm_103a; ptxas never emits FFMA2 from C++) ----
__device__ __forceinline__ u64 pack2(float lo, float hi) {
    u64 r; asm("mov.b64 %0, {%1, %2};" : "=l"(r) : "f"(lo), "f"(hi)); return r;
}
__device__ __forceinline__ u64 fma2(u64 a, u64 b, u64 c) {
    u64 d; asm("fma.rn.f32x2 %0, %1, %2, %3;" : "=l"(d) : "l"(a), "l"(b), "l"(c));
    return d;
}
__device__ __forceinline__ void unpack2(u64 v, float& lo, float& hi) {
    asm("mov.b64 {%0, %1}, %2;" : "=f"(lo), "=f"(hi) : "l"(v));
}
__device__ __forceinline__ u64 relu2(u64 v) {
    float lo, hi; unpack2(v, lo, hi);
    return pack2(fmaxf(lo, 0.0f), fmaxf(hi, 0.0f));
}

// Paired-image intermediates: element [pair][...] = (img 2p value, img 2p+1 value)
__device__ u64 g_h1_2[(size_t)NPAIR * 10 * 361];   // conv1 out
__device__ u64 g_h2_2[(size_t)NPAIR * 20 * 100];   // conv2 out

// Pre-packed (w,w) weights in global (read via LDG -> LSU pipe, not LDS pipe)
__device__ u64 g_w1p[1000];
__device__ u64 g_w2p[20000];
__device__ u64 g_w3p[10000];
__device__ u64 g_wfp[7200];

__global__ void pack_weights_kernel(
    const float* __restrict__ w1, const float* __restrict__ w2,
    const float* __restrict__ w3, const float* __restrict__ wf)
{
    const int i = blockIdx.x * 256 + threadIdx.x;
    if (i < 1000)  g_w1p[i] = pack2(w1[i], w1[i]);
    if (i < 20000) g_w2p[i] = pack2(w2[i], w2[i]);
    if (i < 10000) g_w3p[i] = pack2(w3[i], w3[i]);
    if (i < 7200)  g_wfp[i] = pack2(wf[i], wf[i]);
}

// ---------------------------------------------------------------------------
// conv1: [1,28,28] -> relu -> [10,19,19], k10. One block per image PAIR.
// 96 threads, 95 active: thread = (ocg 0..4 [2 oc], oy 0..18).
// Input pitch 29 u64 (conflict-free). Weights via LDG.128 from g_w1p.
// ---------------------------------------------------------------------------
__global__ __launch_bounds__(96) void conv1_kernel(
    const float* __restrict__ x, const float* __restrict__ b1)
{
    __shared__ u64 s_in2[28 * 29];
    const int bid = blockIdx.x;
    const int tid = threadIdx.x;

    const float* x0 = x + (size_t)(2 * bid) * 784;
    const float* x1 = x0 + 784;
    for (int i = tid; i < 784; i += 96) {
        const int r = i / 28, c = i % 28;
        s_in2[r * 29 + c] = pack2(x0[i], x1[i]);
    }
    __syncthreads();

    if (tid < 95) {
        const int ocg = tid / 19, oy = tid % 19;
        const int oc0 = 2 * ocg;
        const float bv0 = __ldg(&b1[oc0]), bv1 = __ldg(&b1[oc0 + 1]);
        const u64 bi0 = pack2(bv0, bv0), bi1 = pack2(bv1, bv1);
        u64* op0 = &g_h1_2[((size_t)bid * 10 + oc0) * 361 + oy * 19];

        // pass A: outputs q = 0..9
        {
            u64 a0[10], a1[10];
            #pragma unroll
            for (int q = 0; q < 10; q++) { a0[q] = bi0; a1[q] = bi1; }
            for (int ky = 0; ky < 10; ky++) {
                u64 iv[19];
                const u64* rp = &s_in2[(oy + ky) * 29];
                #pragma unroll
                for (int j = 0; j < 19; j++) iv[j] = rp[j];
                const u64* w0p = &g_w1p[oc0 * 100 + ky * 10];
                const u64* w1p = w0p + 100;
                #pragma unroll
                for (int k2 = 0; k2 < 5; k2++) {
                    const ulonglong2 wa = __ldg((const ulonglong2*)(w0p + 2 * k2));
                    const ulonglong2 wb = __ldg((const ulonglong2*)(w1p + 2 * k2));
                    #pragma unroll
                    for (int q = 0; q < 10; q++) {
                        a0[q] = fma2(iv[q + 2 * k2],     wa.x, a0[q]);
                        a0[q] = fma2(iv[q + 2 * k2 + 1], wa.y, a0[q]);
                        a1[q] = fma2(iv[q + 2 * k2],     wb.x, a1[q]);
                        a1[q] = fma2(iv[q + 2 * k2 + 1], wb.y, a1[q]);
                    }
                }
            }
            #pragma unroll
            for (int q = 0; q < 10; q++) {
                op0[q]       = relu2(a0[q]);
                op0[361 + q] = relu2(a1[q]);
            }
        }
        // pass B: outputs q = 10..18
        {
            u64 a0[9], a1[9];
            #pragma unroll
            for (int q = 0; q < 9; q++) { a0[q] = bi0; a1[q] = bi1; }
            for (int ky = 0; ky < 10; ky++) {
                u64 iv[18];
                const u64* rp = &s_in2[(oy + ky) * 29 + 10];
                #pragma unroll
                for (int j = 0; j < 18; j++) iv[j] = rp[j];
                const u64* w0p = &g_w1p[oc0 * 100 + ky * 10];
                const u64* w1p = w0p + 100;
                #pragma unroll
                for (int k2 = 0; k2 < 5; k2++) {
                    const ulonglong2 wa = __ldg((const ulonglong2*)(w0p + 2 * k2));
                    const ulonglong2 wb = __ldg((const ulonglong2*)(w1p + 2 * k2));
                    #pragma unroll
                    for (int q = 0; q < 9; q++) {
                        a0[q] = fma2(iv[q + 2 * k2],     wa.x, a0[q]);
                        a0[q] = fma2(iv[q + 2 * k2 + 1], wa.y, a0[q]);
                        a1[q] = fma2(iv[q + 2 * k2],     wb.x, a1[q]);
                        a1[q] = fma2(iv[q + 2 * k2 + 1], wb.y, a1[q]);
                    }
                }
            }
            #pragma unroll
            for (int q = 0; q < 9; q++) {
                op0[10 + q]  = relu2(a0[q]);
                op0[371 + q] = relu2(a1[q]);
            }
        }
    }
}

// ---------------------------------------------------------------------------
// conv2: [10,19,19] -> relu -> [20,10,10], k10. One block per image PAIR.
// 128 threads, 100 active: thread = (ocg 0..9 [2 oc], oy 0..9).
// Software pipeline: prefetch c+1 (LDG->regs), compute c (smem), STS, 1 sync/c.
// Weights via LDG.128 from g_w2p (off the LDS pipe).
// ---------------------------------------------------------------------------
__global__ __launch_bounds__(128) void conv2_kernel(const float* __restrict__ b2)
{
    __shared__ u64 s_in2[2][361];
    const int bid = blockIdx.x;
    const int tid = threadIdx.x;
    const bool act = tid < 100;
    const int ocg = tid / 10, oy = tid % 10;
    const int oc0 = 2 * ocg;
    const u64* h1p = &g_h1_2[(size_t)bid * 3610];

    // stage c = 0
    {
        s_in2[0][tid]       = h1p[tid];
        s_in2[0][tid + 128] = h1p[tid + 128];
        if (tid < 105) s_in2[0][tid + 256] = h1p[tid + 256];
    }

    u64 a0[10], a1[10];
    {
        const float bv0 = __ldg(&b2[oc0]), bv1 = __ldg(&b2[oc0 + 1]);
        const u64 bi0 = pack2(bv0, bv0), bi1 = pack2(bv1, bv1);
        #pragma unroll
        for (int q = 0; q < 10; q++) { a0[q] = bi0; a1[q] = bi1; }
    }
    __syncthreads();

    for (int c = 0; c < 10; c++) {
        // prefetch next channel into regs (latency hidden by compute)
        u64 r0 = 0, r1 = 0, r2 = 0;
        if (c < 9) {
            const u64* np = h1p + (c + 1) * 361;
            r0 = np[tid];
            r1 = np[tid + 128];
            if (tid < 105) r2 = np[tid + 256];
        }

        if (act) {
            const u64* buf = s_in2[c & 1];
            for (int ky = 0; ky < 10; ky++) {
                u64 iv[19];
                const u64* rp = &buf[(oy + ky) * 19];
                #pragma unroll
                for (int j = 0; j < 19; j++) iv[j] = rp[j];
                const u64* w0p = &g_w2p[oc0 * 1000 + c * 100 + ky * 10];
                const u64* w1p = w0p + 1000;
                #pragma unroll
                for (int k2 = 0; k2 < 5; k2++) {
                    const ulonglong2 wa = __ldg((const ulonglong2*)(w0p + 2 * k2));
                    const ulonglong2 wb = __ldg((const ulonglong2*)(w1p + 2 * k2));
                    #pragma unroll
                    for (int q = 0; q < 10; q++) {
                        a0[q] = fma2(iv[q + 2 * k2],     wa.x, a0[q]);
                        a0[q] = fma2(iv[q + 2 * k2 + 1], wa.y, a0[q]);
                        a1[q] = fma2(iv[q + 2 * k2],     wb.x, a1[q]);
                        a1[q] = fma2(iv[q + 2 * k2 + 1], wb.y, a1[q]);
                    }
                }
            }
        }

        if (c < 9) {
            u64* nb = s_in2[(c + 1) & 1];
            nb[tid]       = r0;
            nb[tid + 128] = r1;
            if (tid < 105) nb[tid + 256] = r2;
        }
        __syncthreads();
    }

    if (act) {
        u64* op = &g_h2_2[((size_t)bid * 20 + oc0) * 100 + oy * 10];
        #pragma unroll
        for (int q = 0; q < 10; q++) {
            op[q]       = relu2(a0[q]);
            op[100 + q] = relu2(a1[q]);
        }
    }
}

// ---------------------------------------------------------------------------
// conv3 + FC: [20,10,10] -> relu conv [20,6,6] (k5) -> 720 -> out[10].
// One block per 2 image pairs (4 images), 128 threads.
// ALL 20 input channels preloaded (35 KB smem) -> zero barriers in the conv.
// Weights via LDG from g_w3p / g_wfp.
// ---------------------------------------------------------------------------
__global__ __launch_bounds__(128) void conv3_fc_kernel(
    const float* __restrict__ b3, const float* __restrict__ bf,
    float* __restrict__ out)
{
    __shared__ u64 s_in2[2][2200];   // [pair][c*110 + row*11 + col], pitch 11
    __shared__ u64 s_h2[2][720];     // conv3 relu out per pair
    __shared__ float s_rlo[4][10], s_rhi[4][10];

    const int bid = blockIdx.x;
    const int tid = threadIdx.x;
    const int p0 = 2 * bid;

    // load all input channels for both pairs
    for (int i = tid; i < 4000; i += 128) {
        const int pq = i / 2000, rem = i % 2000;
        const int c = rem / 100, j = rem % 100;
        s_in2[pq][c * 110 + (j / 10) * 11 + (j % 10)] =
            g_h2_2[((size_t)(p0 + pq) * 20 + c) * 100 + j];
    }

    const bool act = tid < 120;
    const int pp  = tid / 60;
    const int r   = tid % 60;
    const int ocg = r / 6, oy = r % 6;
    const int oc0 = 2 * ocg;

    u64 a0[6], a1[6];
    if (act) {
        const float bv0 = __ldg(&b3[oc0]), bv1 = __ldg(&b3[oc0 + 1]);
        const u64 bi0 = pack2(bv0, bv0), bi1 = pack2(bv1, bv1);
        #pragma unroll
        for (int q = 0; q < 6; q++) { a0[q] = bi0; a1[q] = bi1; }
    }
    __syncthreads();

    if (act) {
        for (int c = 0; c < 20; c++) {
            const u64* base = &s_in2[pp][c * 110];
            #pragma unroll
            for (int ky = 0; ky < 5; ky++) {
                u64 iv[10];
                const u64* rp = &base[(oy + ky) * 11];
                #pragma unroll
                for (int j = 0; j < 10; j++) iv[j] = rp[j];
                const u64* w0p = &g_w3p[oc0 * 500 + c * 25 + ky * 5];
                const u64* w1p = w0p + 500;
                #pragma unroll
                for (int kx = 0; kx < 5; kx++) {
                    const u64 w0  = __ldg(w0p + kx);
                    const u64 w1v = __ldg(w1p + kx);
                    #pragma unroll
                    for (int q = 0; q < 6; q++) {
                        a0[q] = fma2(iv[q + kx], w0,  a0[q]);
                        a1[q] = fma2(iv[q + kx], w1v, a1[q]);
                    }
                }
            }
        }
    }

    __syncthreads();
    if (act) {
        #pragma unroll
        for (int q = 0; q < 6; q++) {
            s_h2[pp][oc0 * 36 + oy * 6 + q]       = relu2(a0[q]);
            s_h2[pp][(oc0 + 1) * 36 + oy * 6 + q] = relu2(a1[q]);
        }
    }
    __syncthreads();

    // ---- FC: threads 0-63 -> pair p0, 64-127 -> pair p0+1 ----
    {
        const int fpp = tid >> 6;
        const int j0  = tid & 63;
        u64 acc[10];
        #pragma unroll
        for (int o = 0; o < 10; o++) acc[o] = 0ULL;
        for (int j = j0; j < 720; j += 64) {
            const u64 v2 = s_h2[fpp][j];
            #pragma unroll
            for (int o = 0; o < 10; o++)
                acc[o] = fma2(v2, __ldg(&g_wfp[o * 720 + j]), acc[o]);
        }
        const int wid = tid >> 5;
        #pragma unroll
        for (int o = 0; o < 10; o++) {
            float lo, hi; unpack2(acc[o], lo, hi);
            #pragma unroll
            for (int s = 16; s > 0; s >>= 1) {
                lo += __shfl_down_sync(0xffffffffu, lo, s);
                hi += __shfl_down_sync(0xffffffffu, hi, s);
            }
            if ((tid & 31) == 0) { s_rlo[wid][o] = lo; s_rhi[wid][o] = hi; }
        }
    }
    __syncthreads();
    if (tid < 40) {
        const int o  = tid % 10;
        const int im = tid / 10;
        const int fpp  = im >> 1;
        const int half = im & 1;
        const int w0 = 2 * fpp;
        float v;
        if (half == 0) v = s_rlo[w0][o] + s_rlo[w0 + 1][o];
        else           v = s_rhi[w0][o] + s_rhi[w0 + 1][o];
        out[(size_t)(4 * bid + im) * 10 + o] = v + __ldg(&bf[o]);
    }
}

// ---------------------------------------------------------------------------
extern "C" void kernel_launch(void* const* d_in, const int* in_sizes, int n_in,
                              void* d_out, int out_size)
{
    (void)in_sizes; (void)n_in; (void)out_size;
    const float* x  = (const float*)d_in[0];
    const float* w1 = (const float*)d_in[1];
    const float* b1 = (const float*)d_in[2];
    const float* w2 = (const float*)d_in[3];
    const float* b2 = (const float*)d_in[4];
    const float* w3 = (const float*)d_in[5];
    const float* b3 = (const float*)d_in[6];
    const float* wf = (const float*)d_in[7];
    const float* bf = (const float*)d_in[8];
    float* out = (float*)d_out;

    pack_weights_kernel<<<79, 256>>>(w1, w2, w3, wf);
    conv1_kernel<<<NPAIR, 96>>>(x, b1);
    conv2_kernel<<<NPAIR, 128>>>(b2);
    conv3_fc_kernel<<<NPAIR / 2, 128>>>(b3, bf, out);
}